// round 9
// baseline (speedup 1.0000x reference)
#include <cuda_runtime.h>
#include <cstdint>

#define NVEH 16384
#define NT   256
#define H    20

#define VPC   16                 // vehicles per CTA
#define TPC   160                // 2 grps x 80 threads (20 units x 4 gates)
#define NCTA  (NVEH / VPC)       // 1024
#define PPG   4                  // pairs per group (8 vehicles)
#define NPAIR 8                  // pairs per CTA
#define RS    24                 // ull stride per h row (20 used + 4 pad)

typedef unsigned long long ull;

// gW4[(u*4+gq)*25 + slot]: dup'd float2, prescaled (sigmoid gates x0.5, g x1).
//   slot 0 : q-row      (W1*0.025 - W0*0.01)
//   slot 1 : leadpos row (W0*0.01)
//   slot 2 : leadspd row (W2*0.025)
//   slot 3..22 : U rows
//   slot 23: bias, slot 24: D-row weight (W1*0.025)
// gate order gq: 0=i, 1=f, 2=g, 3=o  (col = gq*20 + u)
__device__ float2 gW4[80 * 25];
__device__ float2 gWdD[20];      // dup(0.7*Wd[k])
__device__ float2 gC1v;          // dup(0.7*bd - 0.4)

// ---------- packed f32x2 helpers ----------
__device__ __forceinline__ void ffma2(ull& d, ull a, ull b) {
    asm("fma.rn.f32x2 %0, %1, %2, %0;" : "+l"(d) : "l"(a), "l"(b));
}
__device__ __forceinline__ ull mul2(ull a, ull b) {
    ull r; asm("mul.rn.f32x2 %0, %1, %2;" : "=l"(r) : "l"(a), "l"(b)); return r;
}
__device__ __forceinline__ ull add2(ull a, ull b) {
    ull r; asm("add.rn.f32x2 %0, %1, %2;" : "=l"(r) : "l"(a), "l"(b)); return r;
}
__device__ __forceinline__ ull pack2(float lo, float hi) {
    ull r; asm("mov.b64 %0, {%1, %2};" : "=l"(r) : "f"(lo), "f"(hi)); return r;
}
__device__ __forceinline__ float lo32(ull v) {
    float f; asm("{ .reg .b32 hi; mov.b64 {%0, hi}, %1; }" : "=f"(f) : "l"(v)); return f;
}
__device__ __forceinline__ float hi32(ull v) {
    float f; asm("{ .reg .b32 lo; mov.b64 {lo, %0}, %1; }" : "=f"(f) : "l"(v)); return f;
}
__device__ __forceinline__ float fast_tanh(float x) {
    float y; asm("tanh.approx.f32 %0, %1;" : "=f"(y) : "f"(x)); return y;
}

// ---------- repack ----------
__global__ void repack_kernel(const float* __restrict__ W,
                              const float* __restrict__ U,
                              const float* __restrict__ b,
                              const float* __restrict__ Wd,
                              const float* __restrict__ bd)
{
    int i = blockIdx.x * blockDim.x + threadIdx.x;
    if (i < 80 * 25) {
        int lane = i / 25, slot = i % 25;
        int u = lane >> 2, gq = lane & 3;
        int col = gq * 20 + u;
        float s = (gq == 2) ? 1.0f : 0.5f;
        float w;
        if (slot == 0)       w = W[80 + col] * 0.025f - W[col] * 0.01f;
        else if (slot == 1)  w = W[col] * 0.01f;
        else if (slot == 2)  w = W[160 + col] * 0.025f;
        else if (slot < 23)  w = U[(slot - 3) * 80 + col];
        else if (slot == 23) w = b[col];
        else                 w = W[80 + col] * 0.025f;
        w *= s;
        gW4[i] = make_float2(w, w);
    }
    if (i < 20)  { float a = 0.7f * Wd[i]; gWdD[i] = make_float2(a, a); }
    if (i == 20) { float v = 0.7f * bd[0] - 0.4f; gC1v = make_float2(v, v); }
}

__global__ __launch_bounds__(TPC, 4)
void rnncf_kernel(const float* __restrict__ lead_inputs,  // (NVEH, NT, 2)
                  const float* __restrict__ init_state,   // (NVEH, 2)
                  const float* __restrict__ h0,           // (NVEH, H)
                  const float* __restrict__ c0,           // (NVEH, H)
                  float* __restrict__ out,
                  int out_size)
{
    __shared__ ull   hbuf[2][NPAIR * RS];      // h pairs, double buffered
    __shared__ float sxl[2][2][VPC];           // staged lead: [buf][{pos,spd}][veh]
    __shared__ ull   wdsm[20];                 // dup'd 0.7*Wd

    const int tid  = threadIdx.x;
    const int grp  = tid / 80;
    const int r    = tid % 80;
    const int u    = r >> 2;
    const int gq   = r & 3;
    const int pb   = grp * PPG;                // pair base in CTA
    const int vbase = blockIdx.x * VPC + grp * (2 * PPG);

    // ---- this thread's gate weights into registers ----
    ull wt[23], bias, wD;
    {
        const ull* blk = reinterpret_cast<const ull*>(gW4) + (u * 4 + gq) * 25;
#pragma unroll
        for (int k = 0; k < 23; ++k) wt[k] = blk[k];
        bias = blk[23]; wD = blk[24];
    }
    if (tid < 20) wdsm[tid] = reinterpret_cast<const ull*>(gWdD)[tid];
    const ull cinit = *reinterpret_cast<const ull*>(&gC1v);
    const float gm = (gq == 2) ? 1.0f : 0.5f;
    const float gc = (gq == 2) ? 0.0f : 0.5f;

    // ---- per-pair state ----
    ull cc[PPG], qq[PPG], bb[PPG];
#pragma unroll
    for (int p = 0; p < PPG; ++p) {
        const int vA = vbase + 2 * p, vB = vA + 1;
        float pA = init_state[2 * vA], sA = init_state[2 * vA + 1];
        float pB = init_state[2 * vB], sB = init_state[2 * vB + 1];
        qq[p] = pack2(pA, pB);
        ull Dp = pack2(sA - pA, sB - pB);
        bb[p] = bias; ffma2(bb[p], wD, Dp);      // bias + D-term folded
        if (gq == 0) {
            cc[p] = pack2(c0[vA * H + u], c0[vB * H + u]);
            hbuf[0][(pb + p) * RS + u] = pack2(h0[vA * H + u], h0[vB * H + u]);
        }
    }
    if (tid < VPC) {
        float2 L = reinterpret_cast<const float2*>(lead_inputs)
                       [(size_t)(blockIdx.x * VPC + tid) * NT];
        sxl[0][0][tid] = L.x; sxl[0][1][tid] = L.y;
    }
    __syncthreads();

    const float2* lead2 = reinterpret_cast<const float2*>(lead_inputs);
    const bool extras = (out_size >= NT * NVEH + NVEH + 2 * NVEH * H);

#pragma unroll 1
    for (int t = 0; t < NT; ++t) {
        const int cur = t & 1, nxt = cur ^ 1;
        const ull* rb = hbuf[cur];
        ull*       wb = hbuf[nxt];

        // prefetch next lead (stored to smem at end of step)
        float2 Lnext = make_float2(0.f, 0.f);
        if (tid < VPC) {
            int tn = (t + 1 < NT) ? (t + 1) : (NT - 1);
            Lnext = lead2[(size_t)(blockIdx.x * VPC + tid) * NT + tn];
        }

#pragma unroll 2
        for (int p = 0; p < PPG; ++p) {
            const ull* row = rb + (pb + p) * RS;

            // ---- Wd dot on h(t): quad-split partials + butterfly ----
            if (t > 0) {
                const ull* dh = row + gq * 5;
                ull pa = 0ull;
#pragma unroll
                for (int j = 0; j < 5; ++j) ffma2(pa, wdsm[gq * 5 + j], dh[j]);
                ull s1 = add2(pa, __shfl_xor_sync(0xffffffffu, pa, 1));
                ull s2 = add2(s1, __shfl_xor_sync(0xffffffffu, s1, 2));
                qq[p] = add2(qq[p], add2(s2, cinit));     // q += 0.7*dot + c1
                if (r == 0)
                    *reinterpret_cast<float2*>(
                        out + (size_t)(t - 1) * NVEH + vbase + 2 * p) =
                        make_float2(lo32(qq[p]), hi32(qq[p]));
            }

            // ---- GEMM: 23 rows, one gate, pair-packed, zero MOVs ----
            ull a = bb[p];
            ffma2(a, wt[0], qq[p]);
            {
                ull lpz = *reinterpret_cast<const ull*>(&sxl[cur][0][2 * (pb + p)]);
                ull lsz = *reinterpret_cast<const ull*>(&sxl[cur][1][2 * (pb + p)]);
                ffma2(a, wt[1], lpz);
                ffma2(a, wt[2], lsz);
            }
            {
                const ulonglong2* rp = reinterpret_cast<const ulonglong2*>(row);
#pragma unroll
                for (int j = 0; j < 10; ++j) {
                    ulonglong2 hv = rp[j];
                    ffma2(a, wt[3 + 2 * j], hv.x);
                    ffma2(a, wt[4 + 2 * j], hv.y);
                }
            }

            // own gate activation (affine by gate type)
            ull g = pack2(fmaf(gm, fast_tanh(lo32(a)), gc),
                          fmaf(gm, fast_tanh(hi32(a)), gc));
            // gather quad gates: lane0 roles -> g=i, gb=f, gx=g, gd=o
            ull gb = __shfl_xor_sync(0xffffffffu, g, 1);
            ull gx = __shfl_xor_sync(0xffffffffu, g, 2);
            ull gd = __shfl_xor_sync(0xffffffffu, gb, 2);
            if (gq == 0) {
                ull cn = mul2(g, gx);            // sig(i)*tanh(g)
                ffma2(cn, gb, cc[p]);            // + sig(f)*c
                cc[p] = cn;
                ull tc = pack2(fast_tanh(lo32(cn)), fast_tanh(hi32(cn)));
                wb[(pb + p) * RS + u] = mul2(gd, tc);   // h(t+1)
            }
        }

        if (tid < VPC) { sxl[nxt][0][tid] = Lnext.x; sxl[nxt][1][tid] = Lnext.y; }
        __syncthreads();
    }

    // ---- epilogue: dot on h(NT), final output + extras ----
    const ull* fb = hbuf[NT & 1];
    float* hout  = out + (size_t)NT * NVEH + NVEH;
    float* cout2 = hout + (size_t)NVEH * H;

#pragma unroll
    for (int p = 0; p < PPG; ++p) {
        const ull* row = fb + (pb + p) * RS;
        const int vA = vbase + 2 * p, vB = vA + 1;

        const ull* dh = row + gq * 5;
        ull pa = 0ull;
#pragma unroll
        for (int j = 0; j < 5; ++j) ffma2(pa, wdsm[gq * 5 + j], dh[j]);
        ull s1 = add2(pa, __shfl_xor_sync(0xffffffffu, pa, 1));
        ull s2 = add2(s1, __shfl_xor_sync(0xffffffffu, s1, 2));
        qq[p] = add2(qq[p], add2(s2, cinit));
        if (r == 0)
            *reinterpret_cast<float2*>(
                out + (size_t)(NT - 1) * NVEH + vA) =
                make_float2(lo32(qq[p]), hi32(qq[p]));

        if (extras) {
            if (r == 0) {
                float DA = init_state[2 * vA + 1] - init_state[2 * vA];
                float DB = init_state[2 * vB + 1] - init_state[2 * vB];
                out[(size_t)NT * NVEH + vA] = lo32(qq[p]) + DA;
                out[(size_t)NT * NVEH + vB] = hi32(qq[p]) + DB;
            }
            if (gq == 0) {
                ull hv = row[u];
                hout[vA * H + u] = lo32(hv);
                hout[vB * H + u] = hi32(hv);
                cout2[vA * H + u] = lo32(cc[p]);
                cout2[vB * H + u] = hi32(cc[p]);
            }
        }
    }
}

extern "C" void kernel_launch(void* const* d_in, const int* in_sizes, int n_in,
                              void* d_out, int out_size) {
    const float* lead_inputs = (const float*)d_in[0];
    const float* init_state  = (const float*)d_in[1];
    const float* h0          = (const float*)d_in[2];
    const float* c0          = (const float*)d_in[3];
    const float* W           = (const float*)d_in[4];
    const float* U           = (const float*)d_in[5];
    const float* b           = (const float*)d_in[6];
    const float* Wd          = (const float*)d_in[7];
    const float* bd          = (const float*)d_in[8];

    repack_kernel<<<2, 1024>>>(W, U, b, Wd, bd);
    rnncf_kernel<<<NCTA, TPC>>>(lead_inputs, init_state, h0, c0,
                                (float*)d_out, out_size);
}

// round 10
// speedup vs baseline: 2.1125x; 2.1125x over previous
#include <cuda_runtime.h>
#include <cstdint>

#define NVEH 16384
#define NT   256
#define H    20

#define VPC   64                 // vehicles per CTA
#define TPC   160                // 4 grps x 40 (20 units x 2 parities)
#define NCTA  (NVEH / VPC)       // 256
#define PPG   8                  // pairs per grp (16 vehicles)
#define NPAIR 32                 // pairs per CTA
#define RS    24                 // ull per h row (20 used + 4 pad)

typedef unsigned long long ull;

// gWp[lane*48 + slot], lane = u*2+par. Chains: A = par? f : i, B = par? o : g.
//   slot 0..22 : chain A rows (x0,x1,x2, U0..U19), slot 23: A bias
//   slot 24..46: chain B rows,                     slot 47: B bias
// All weights duplicated into both f32x2 lanes; sigmoid gates prescaled x0.5.
__device__ float2 gWp[40 * 48];
__device__ float  gWdv[24];      // Wd[0..19], bd at [20]

// ---------- packed f32x2 helpers ----------
__device__ __forceinline__ void ffma2(ull& d, ull a, ull b) {
    asm("fma.rn.f32x2 %0, %1, %2, %0;" : "+l"(d) : "l"(a), "l"(b));
}
__device__ __forceinline__ ull mul2(ull a, ull b) {
    ull r; asm("mul.rn.f32x2 %0, %1, %2;" : "=l"(r) : "l"(a), "l"(b)); return r;
}
__device__ __forceinline__ ull pack2(float lo, float hi) {
    ull r; asm("mov.b64 %0, {%1, %2};" : "=l"(r) : "f"(lo), "f"(hi)); return r;
}
__device__ __forceinline__ float lo32(ull v) {
    float f; asm("{ .reg .b32 hi; mov.b64 {%0, hi}, %1; }" : "=f"(f) : "l"(v)); return f;
}
__device__ __forceinline__ float hi32(ull v) {
    float f; asm("{ .reg .b32 lo; mov.b64 {lo, %0}, %1; }" : "=f"(f) : "l"(v)); return f;
}
__device__ __forceinline__ float fast_tanh(float x) {
    float y; asm("tanh.approx.f32 %0, %1;" : "=f"(y) : "f"(x)); return y;
}

// ---------- repack ----------
__global__ void repack_kernel(const float* __restrict__ W,
                              const float* __restrict__ U,
                              const float* __restrict__ b,
                              const float* __restrict__ Wd,
                              const float* __restrict__ bd)
{
    int i = blockIdx.x * blockDim.x + threadIdx.x;
    if (i < 40 * 48) {
        int lane = i / 48, s = i % 48;
        int u = lane >> 1, par = lane & 1;
        int chain = s / 24, loc = s % 24;
        // gate index: chainA -> par? f(1) : i(0); chainB -> par? o(3) : g(2)
        int gidx = chain == 0 ? (par ? 1 : 0) : (par ? 3 : 2);
        int col = gidx * 20 + u;
        float sc = (gidx == 2) ? 1.0f : 0.5f;
        float w;
        if (loc < 3)       w = W[loc * 80 + col];
        else if (loc < 23) w = U[(loc - 3) * 80 + col];
        else               w = b[col];
        w *= sc;
        gWp[i] = make_float2(w, w);
    }
    if (i < 20)  gWdv[i]  = Wd[i];
    if (i == 20) gWdv[20] = bd[0];
}

__global__ __launch_bounds__(TPC, 2)
void rnncf_kernel(const float* __restrict__ lead_inputs,  // (NVEH, NT, 2)
                  const float* __restrict__ init_state,   // (NVEH, 2)
                  const float* __restrict__ h0,           // (NVEH, H)
                  const float* __restrict__ c0,           // (NVEH, H)
                  float* __restrict__ out,
                  int out_size)
{
    __shared__ ull hb[2][NPAIR * RS];                 // h pairs, double buffered
    __shared__ __align__(16) float sx[2][3][VPC];     // x rows: [buf][slot][veh]

    const int tid = threadIdx.x;
    const int grp = tid / 40;
    const int r   = tid % 40;
    const int u   = r >> 1;
    const int par = r & 1;
    const int pb  = grp * PPG;
    const int vcta = blockIdx.x * VPC;

    // ---- weights into registers ----
    ull wA[23], wB[23], bA, bB;
    {
        const ull* blk = reinterpret_cast<const ull*>(gWp) + r * 48;
#pragma unroll
        for (int k = 0; k < 23; ++k) { wA[k] = blk[k]; wB[k] = blk[24 + k]; }
        bA = blk[23]; bB = blk[47];
    }

    // ---- init state ----
    ull cc[PPG];        // c pairs, live on par1 only
#pragma unroll
    for (int p = 0; p < PPG; ++p) {
        const int vA = vcta + 2 * (pb + p);
        if (par) cc[p] = pack2(c0[vA * H + u], c0[(vA + 1) * H + u]);
        else     hb[0][(pb + p) * RS + u] =
                     pack2(h0[vA * H + u], h0[(vA + 1) * H + u]);
    }

    // driver state (threads 0..63 ~ vehicles)
    float pos = 0.f, spd = 0.f, bdv = 0.f;
    float wdr[20];
    const float2* mylead = nullptr;
    if (tid < VPC) {
        const int gv = vcta + tid;
        pos = init_state[2 * gv];
        spd = init_state[2 * gv + 1];
        mylead = reinterpret_cast<const float2*>(lead_inputs) + (size_t)gv * NT;
        float2 l0 = mylead[0];
        sx[0][0][tid] = (l0.x - pos) * 0.01f;
        sx[0][1][tid] = spd * 0.025f;
        sx[0][2][tid] = l0.y * 0.025f;
#pragma unroll
        for (int j = 0; j < 20; ++j) wdr[j] = gWdv[j];
        bdv = gWdv[20];
    }
    __syncthreads();

    const bool extras = (out_size >= NT * NVEH + NVEH + 2 * NVEH * H);

#pragma unroll 1
    for (int t = 0; t < NT; ++t) {
        const int cur = t & 1, nxb = cur ^ 1;
        const ull* rbh = hb[cur];
        ull*       wbh = hb[nxb];

        float2 nl = make_float2(0.f, 0.f);
        if (tid < VPC) {
            int tn = (t + 1 < NT) ? (t + 1) : (NT - 1);
            nl = mylead[tn];
        }

        // ---- GEMM + gates, pair-packed, zero-MOV inner loop ----
#pragma unroll 2
        for (int p = 0; p < PPG; ++p) {
            const int gp = pb + p;
            const ull* row = rbh + gp * RS;
            ull x0 = *reinterpret_cast<const ull*>(&sx[cur][0][2 * gp]);
            ull x1 = *reinterpret_cast<const ull*>(&sx[cur][1][2 * gp]);
            ull x2 = *reinterpret_cast<const ull*>(&sx[cur][2][2 * gp]);

            ull aA = bA, aB = bB;
            ffma2(aA, wA[0], x0); ffma2(aB, wB[0], x0);
            ffma2(aA, wA[1], x1); ffma2(aB, wB[1], x1);
            ffma2(aA, wA[2], x2); ffma2(aB, wB[2], x2);
            const ulonglong2* rp = reinterpret_cast<const ulonglong2*>(row);
#pragma unroll
            for (int j = 0; j < 10; ++j) {
                ulonglong2 hv = rp[j];
                ffma2(aA, wA[3 + 2 * j], hv.x); ffma2(aB, wB[3 + 2 * j], hv.x);
                ffma2(aA, wA[4 + 2 * j], hv.y); ffma2(aB, wB[4 + 2 * j], hv.y);
            }

            // activations: chainA sigmoid-type both parities (i / f);
            // chainB: par0 -> tanh(g), par1 -> sig(o)
            float tA0 = fast_tanh(lo32(aA)), tA1 = fast_tanh(hi32(aA));
            float tB0 = fast_tanh(lo32(aB)), tB1 = fast_tanh(hi32(aB));
            ull gA = pack2(fmaf(0.5f, tA0, 0.5f), fmaf(0.5f, tA1, 0.5f)); // si / sf
            ull gB = par ? pack2(fmaf(0.5f, tB0, 0.5f), fmaf(0.5f, tB1, 0.5f))
                         : pack2(tB0, tB1);                               // so / tg
            ull m = par ? gA : mul2(gA, gB);     // par0 sends si*tg
            ull got = __shfl_xor_sync(0xffffffffu, m, 1);
            if (par) {
                ull cn = got;                    // si*tg (from par0)
                ffma2(cn, gA, cc[p]);            // + sf*c
                cc[p] = cn;
                ull th = pack2(fast_tanh(lo32(cn)), fast_tanh(hi32(cn)));
                wbh[gp * RS + u] = mul2(gB, th); // h(t+1) = so * tanh(c)
            }
        }
        __syncthreads();

        // ---- driver phase: Wd dot on h(t+1), pos/spd, out, x(t+1) ----
        if (tid < VPC) {
            const int lane = tid & 1;
            const float4* p4 =
                reinterpret_cast<const float4*>(wbh + (tid >> 1) * RS);
            float s0 = bdv, s1 = 0.f;
#pragma unroll
            for (int j = 0; j < 10; ++j) {
                float4 f = p4[j];
                float vlo = lane ? f.y : f.x;    // h[2j]
                float vhi = lane ? f.w : f.z;    // h[2j+1]
                s0 = fmaf(vlo, wdr[2 * j], s0);
                s1 = fmaf(vhi, wdr[2 * j + 1], s1);
            }
            float a = fmaf(7.0f, s0 + s1, -4.0f);
            spd = fmaf(0.1f, a, spd);
            pos = fmaf(0.1f, a, pos);
            out[(size_t)t * NVEH + vcta + tid] = pos;
            sx[nxb][0][tid] = (nl.x - pos) * 0.01f;
            sx[nxb][1][tid] = spd * 0.025f;
            sx[nxb][2][tid] = nl.y * 0.025f;
        }
        __syncthreads();
    }

    // ---- extras ----
    if (extras) {
        if (tid < VPC)
            out[(size_t)NT * NVEH + vcta + tid] = spd;
        float* hout  = out + (size_t)NT * NVEH + NVEH;
        float* cout2 = hout + (size_t)NVEH * H;
        const ull* fb = hb[NT & 1];              // h(NT) buffer (NT even -> hb[0])
#pragma unroll
        for (int p = 0; p < PPG; ++p) {
            const int vA = vcta + 2 * (pb + p);
            if (par) {
                cout2[vA * H + u]       = lo32(cc[p]);
                cout2[(vA + 1) * H + u] = hi32(cc[p]);
            } else {
                ull hv = fb[(pb + p) * RS + u];
                hout[vA * H + u]        = lo32(hv);
                hout[(vA + 1) * H + u]  = hi32(hv);
            }
        }
    }
}

extern "C" void kernel_launch(void* const* d_in, const int* in_sizes, int n_in,
                              void* d_out, int out_size) {
    const float* lead_inputs = (const float*)d_in[0];
    const float* init_state  = (const float*)d_in[1];
    const float* h0          = (const float*)d_in[2];
    const float* c0          = (const float*)d_in[3];
    const float* W           = (const float*)d_in[4];
    const float* U           = (const float*)d_in[5];
    const float* b           = (const float*)d_in[6];
    const float* Wd          = (const float*)d_in[7];
    const float* bd          = (const float*)d_in[8];

    repack_kernel<<<2, 1024>>>(W, U, b, Wd, bd);
    rnncf_kernel<<<NCTA, TPC>>>(lead_inputs, init_state, h0, c0,
                                (float*)d_out, out_size);
}